// round 2
// baseline (speedup 1.0000x reference)
#include <cuda_runtime.h>
#include <math.h>
#include <stdint.h>

// Problem sizes (fixed by the dataset)
#define NN 100000
#define EE 500000

// Scratch (device globals; allocation-free per harness rules)
__device__ float g_cnt[NN];
__device__ float g_sum1[(size_t)NN * 128];
__device__ float g_sum2[(size_t)NN * 128];
__device__ float g_proj[(size_t)NN * 128];
__device__ float g_srcF[(size_t)EE * 128];
__device__ float g_dstF[(size_t)EE * 128];

__device__ __forceinline__ float4 ldg4(const float* p) {
    return __ldg((const float4*)p);
}

// Vectorized global reduction (no return) — 1 op per 16B instead of 4 scalar atomics.
__device__ __forceinline__ void red4(float* p, float4 v) {
    asm volatile("red.global.add.v4.f32 [%0], {%1,%2,%3,%4};"
                 :: "l"(p), "f"(v.x), "f"(v.y), "f"(v.z), "f"(v.w) : "memory");
}

// ---------------------------------------------------------------------------
// Zero cnt + sum1 + sum2
// ---------------------------------------------------------------------------
__global__ void k_zero(float* cnt, float* s1, float* s2, int n) {
    int i = blockIdx.x * blockDim.x + threadIdx.x;
    int stride = gridDim.x * blockDim.x;
    int t4 = n * 32;  // n*128 floats = n*32 float4
    float4 z = make_float4(0.f, 0.f, 0.f, 0.f);
    for (int j = i; j < t4; j += stride) {
        ((float4*)s1)[j] = z;
        ((float4*)s2)[j] = z;
    }
    for (int j = i; j < n; j += stride) cnt[j] = 0.f;
}

// ---------------------------------------------------------------------------
// Layer-1 aggregation: sum1[src] += [nfeat[dst], efeat]; sum1[dst] += [nfeat[src], efeat]
// plus degree counts. One warp per edge (grid-stride).
// ---------------------------------------------------------------------------
__global__ void k_agg1(const float* __restrict__ nfeat, const float* __restrict__ efeat,
                       const int* __restrict__ src, const int* __restrict__ dst,
                       float* sum1, float* cnt, int E) {
    int warp = (blockIdx.x * blockDim.x + threadIdx.x) >> 5;
    int lane = threadIdx.x & 31;
    int nw = (gridDim.x * blockDim.x) >> 5;
    for (int e = warp; e < E; e += nw) {
        int s = __ldg(&src[e]);
        int d = __ldg(&dst[e]);
        float4 vs, vd;
        int off;
        if (lane < 16) {
            off = lane * 4;  // cols [0,64): node-feat part
            vs = ldg4(&nfeat[(size_t)d * 64 + off]);
            vd = ldg4(&nfeat[(size_t)s * 64 + off]);
        } else {
            int q = (lane - 16) * 4;
            off = 64 + q;    // cols [64,128): edge-feat part (shared)
            float4 ef = ldg4(&efeat[(size_t)e * 64 + q]);
            vs = ef; vd = ef;
        }
        red4(&sum1[(size_t)s * 128 + off], vs);
        red4(&sum1[(size_t)d * 128 + off], vd);
        if (lane == 0) {
            atomicAdd(&cnt[s], 1.f);
            atomicAdd(&cnt[d], 1.f);
        }
    }
}

// ---------------------------------------------------------------------------
// Node projection: proj[n] = (sum[n]/max(cnt,1)) @ W[128,128] + b
// Tile: 32 nodes x 128 cols per block, 256 threads, 4x4 register tile.
// ---------------------------------------------------------------------------
__global__ __launch_bounds__(256, 2) void k_proj(
    const float* __restrict__ sum, const float* __restrict__ cnt,
    const float* __restrict__ W, const float* __restrict__ b,
    float* __restrict__ proj, int Nn) {
    __shared__ float A[32 * 128];
    __shared__ float Wc[16 * 128];
    __shared__ float invS[32];
    int tid = threadIdx.x;
    int n0 = blockIdx.x * 32;

    if (tid < 32) {
        int n = n0 + tid;
        float c = 1.f;
        if (n < Nn) c = fmaxf(__ldg(&cnt[n]), 1.f);
        invS[tid] = 1.f / c;
    }
    __syncthreads();
    for (int i = tid; i < 32 * 32; i += 256) {
        int r = i >> 5, q = (i & 31) * 4;
        int n = n0 + r;
        float4 v = make_float4(0.f, 0.f, 0.f, 0.f);
        if (n < Nn) {
            v = ldg4(&sum[(size_t)n * 128 + q]);
            float s = invS[r];
            v.x *= s; v.y *= s; v.z *= s; v.w *= s;
        }
        *(float4*)&A[r * 128 + q] = v;
    }

    int r0 = (tid >> 5) * 4, c0 = (tid & 31) * 4;
    float4 acc[4];
#pragma unroll
    for (int i = 0; i < 4; i++) acc[i] = make_float4(0.f, 0.f, 0.f, 0.f);

    for (int kc = 0; kc < 128; kc += 16) {
        __syncthreads();
        for (int i = tid; i < 512; i += 256) {
            int rr = i >> 5, cc = (i & 31) * 4;
            *(float4*)&Wc[rr * 128 + cc] = ldg4(&W[(size_t)(kc + rr) * 128 + cc]);
        }
        __syncthreads();
#pragma unroll
        for (int kk = 0; kk < 16; kk++) {
            float4 w = *(float4*)&Wc[kk * 128 + c0];
#pragma unroll
            for (int i = 0; i < 4; i++) {
                float a = A[(r0 + i) * 128 + kc + kk];
                acc[i].x += a * w.x; acc[i].y += a * w.y;
                acc[i].z += a * w.z; acc[i].w += a * w.w;
            }
        }
    }

    float4 b4 = ldg4(&b[c0]);
#pragma unroll
    for (int i = 0; i < 4; i++) {
        int n = n0 + r0 + i;
        if (n < Nn) {
            float4 o;
            o.x = acc[i].x + b4.x; o.y = acc[i].y + b4.y;
            o.z = acc[i].z + b4.z; o.w = acc[i].w + b4.w;
            *(float4*)&proj[(size_t)n * 128 + c0] = o;
        }
    }
}

// ---------------------------------------------------------------------------
// Layer-1 edge kernel. A layout per edge (AS=256):
//   [0,64)=nfeat[src], [64,128)=nfeat[dst], [128,192)=efeat, [192,256)=te
// W rows: [0,64) head weights, [64,192) shared (efeat,te) weights.
// out = relu(head@Wh + shared@Wsh + b + proj[node]); also red sum2 for layer 2.
// ---------------------------------------------------------------------------
__global__ __launch_bounds__(256, 2) void k_layer1(
    const float* __restrict__ nfeat, const float* __restrict__ efeat,
    const int* __restrict__ src, const int* __restrict__ dst, const float* __restrict__ ts,
    const float* __restrict__ W, const float* __restrict__ b,
    const float* __restrict__ omega, const float* __restrict__ phase,
    const float* __restrict__ proj, float* __restrict__ outS, float* __restrict__ outD,
    float* __restrict__ sum2, int E) {
    const int AS = 256;
    __shared__ float A[32 * 256];   // 32KB
    __shared__ float Wc[16 * 128];  // 8KB
    __shared__ int sI[32], dI[32];
    __shared__ float tsS[32];
    int tid = threadIdx.x;
    int e0 = blockIdx.x * 32;

    if (tid < 32) {
        int e = e0 + tid;
        bool ok = e < E;
        sI[tid] = ok ? __ldg(&src[e]) : 0;
        dI[tid] = ok ? __ldg(&dst[e]) : 0;
        tsS[tid] = ok ? __ldg(&ts[e]) : 0.f;
    }
    __syncthreads();

    // Fill A: 48 float4 per edge
    for (int i = tid; i < 32 * 48; i += 256) {
        int r = i / 48, p = i % 48;
        int e = e0 + r;
        bool ok = e < E;
        float4 v = make_float4(0.f, 0.f, 0.f, 0.f);
        int col;
        if (p < 16) {
            col = p * 4;
            if (ok) v = ldg4(&nfeat[(size_t)sI[r] * 64 + p * 4]);
        } else if (p < 32) {
            col = 64 + (p - 16) * 4;
            if (ok) v = ldg4(&nfeat[(size_t)dI[r] * 64 + (p - 16) * 4]);
        } else {
            col = 128 + (p - 32) * 4;
            if (ok) v = ldg4(&efeat[(size_t)e * 64 + (p - 32) * 4]);
        }
        *(float4*)&A[r * AS + col] = v;
    }
    // te = cos(ts*omega + phase), cols [192,256)
    for (int i = tid; i < 32 * 16; i += 256) {
        int r = i >> 4, q = (i & 15) * 4;
        float t = tsS[r];
        float4 v;
        v.x = cosf(t * __ldg(&omega[q + 0]) + __ldg(&phase[q + 0]));
        v.y = cosf(t * __ldg(&omega[q + 1]) + __ldg(&phase[q + 1]));
        v.z = cosf(t * __ldg(&omega[q + 2]) + __ldg(&phase[q + 2]));
        v.w = cosf(t * __ldg(&omega[q + 3]) + __ldg(&phase[q + 3]));
        *(float4*)&A[r * AS + 192 + q] = v;
    }

    int r0 = (tid >> 5) * 4, c0 = (tid & 31) * 4;
    float4 aS[4], aD[4], aH[4];
#pragma unroll
    for (int i = 0; i < 4; i++) {
        aS[i] = make_float4(0.f, 0.f, 0.f, 0.f);
        aD[i] = make_float4(0.f, 0.f, 0.f, 0.f);
        aH[i] = make_float4(0.f, 0.f, 0.f, 0.f);
    }

    // Head: W rows [0,64), src uses A cols k, dst uses A cols 64+k
    for (int kc = 0; kc < 64; kc += 16) {
        __syncthreads();
        for (int i = tid; i < 512; i += 256) {
            int rr = i >> 5, cc = (i & 31) * 4;
            *(float4*)&Wc[rr * 128 + cc] = ldg4(&W[(size_t)(kc + rr) * 128 + cc]);
        }
        __syncthreads();
#pragma unroll
        for (int kk = 0; kk < 16; kk++) {
            float4 w = *(float4*)&Wc[kk * 128 + c0];
#pragma unroll
            for (int i = 0; i < 4; i++) {
                float x = A[(r0 + i) * AS + kc + kk];
                float y = A[(r0 + i) * AS + 64 + kc + kk];
                aS[i].x += x * w.x; aS[i].y += x * w.y; aS[i].z += x * w.z; aS[i].w += x * w.w;
                aD[i].x += y * w.x; aD[i].y += y * w.y; aD[i].z += y * w.z; aD[i].w += y * w.w;
            }
        }
    }
    // Shared: W rows [64,192), A cols [128,256) (efeat then te) — computed once
    for (int kc = 0; kc < 128; kc += 16) {
        __syncthreads();
        for (int i = tid; i < 512; i += 256) {
            int rr = i >> 5, cc = (i & 31) * 4;
            *(float4*)&Wc[rr * 128 + cc] = ldg4(&W[(size_t)(64 + kc + rr) * 128 + cc]);
        }
        __syncthreads();
#pragma unroll
        for (int kk = 0; kk < 16; kk++) {
            float4 w = *(float4*)&Wc[kk * 128 + c0];
#pragma unroll
            for (int i = 0; i < 4; i++) {
                float x = A[(r0 + i) * AS + 128 + kc + kk];
                aH[i].x += x * w.x; aH[i].y += x * w.y; aH[i].z += x * w.z; aH[i].w += x * w.w;
            }
        }
    }

    // Epilogue: bias + proj gather + relu; write scratch; fused layer-2 segment-sum
    float4 b4 = ldg4(&b[c0]);
#pragma unroll
    for (int i = 0; i < 4; i++) {
        int r = r0 + i;
        int e = e0 + r;
        if (e < E) {
            int s = sI[r], d = dI[r];
            float4 ps = ldg4(&proj[(size_t)s * 128 + c0]);
            float4 pd = ldg4(&proj[(size_t)d * 128 + c0]);
            float4 os, od;
            os.x = fmaxf(aS[i].x + aH[i].x + b4.x + ps.x, 0.f);
            os.y = fmaxf(aS[i].y + aH[i].y + b4.y + ps.y, 0.f);
            os.z = fmaxf(aS[i].z + aH[i].z + b4.z + ps.z, 0.f);
            os.w = fmaxf(aS[i].w + aH[i].w + b4.w + ps.w, 0.f);
            od.x = fmaxf(aD[i].x + aH[i].x + b4.x + pd.x, 0.f);
            od.y = fmaxf(aD[i].y + aH[i].y + b4.y + pd.y, 0.f);
            od.z = fmaxf(aD[i].z + aH[i].z + b4.z + pd.z, 0.f);
            od.w = fmaxf(aD[i].w + aH[i].w + b4.w + pd.w, 0.f);
            *(float4*)&outS[(size_t)e * 128 + c0] = os;
            *(float4*)&outD[(size_t)e * 128 + c0] = od;
            // Layer-2 aggregation: sum2[src] += dst_out, sum2[dst] += src_out
            red4(&sum2[(size_t)s * 128 + c0], od);
            red4(&sum2[(size_t)d * 128 + c0], os);
        }
    }
}

// ---------------------------------------------------------------------------
// Layer-2 edge kernel. A layout per edge (AS=320):
//   [0,128)=srcF, [128,256)=dstF, [256,320)=te2
// W rows: [0,128) head, [128,192) te (shared). Writes final output.
// ---------------------------------------------------------------------------
__global__ __launch_bounds__(256, 2) void k_layer2(
    const float* __restrict__ fS, const float* __restrict__ fD,
    const int* __restrict__ src, const int* __restrict__ dst, const float* __restrict__ ts,
    const float* __restrict__ W, const float* __restrict__ b,
    const float* __restrict__ omega, const float* __restrict__ phase,
    const float* __restrict__ proj, float* __restrict__ outS, float* __restrict__ outD, int E) {
    const int AS = 320;
    __shared__ float A[32 * 320];   // 40KB
    __shared__ float Wc[16 * 128];  // 8KB  (total 48KB exactly)
    int tid = threadIdx.x;
    int e0 = blockIdx.x * 32;

    // Fill A: 64 float4 per edge (srcF row + dstF row)
    for (int i = tid; i < 32 * 64; i += 256) {
        int r = i >> 6, p = i & 63;
        int e = e0 + r;
        bool ok = e < E;
        float4 v = make_float4(0.f, 0.f, 0.f, 0.f);
        int col;
        if (p < 32) {
            col = p * 4;
            if (ok) v = ldg4(&fS[(size_t)e * 128 + p * 4]);
        } else {
            col = 128 + (p - 32) * 4;
            if (ok) v = ldg4(&fD[(size_t)e * 128 + (p - 32) * 4]);
        }
        *(float4*)&A[r * AS + col] = v;
    }
    // te2, cols [256,320)
    for (int i = tid; i < 32 * 16; i += 256) {
        int r = i >> 4, q = (i & 15) * 4;
        int e = e0 + r;
        float t = (e < E) ? __ldg(&ts[e]) : 0.f;
        float4 v;
        v.x = cosf(t * __ldg(&omega[q + 0]) + __ldg(&phase[q + 0]));
        v.y = cosf(t * __ldg(&omega[q + 1]) + __ldg(&phase[q + 1]));
        v.z = cosf(t * __ldg(&omega[q + 2]) + __ldg(&phase[q + 2]));
        v.w = cosf(t * __ldg(&omega[q + 3]) + __ldg(&phase[q + 3]));
        *(float4*)&A[r * AS + 256 + q] = v;
    }

    int r0 = (tid >> 5) * 4, c0 = (tid & 31) * 4;
    float4 aS[4], aD[4], aH[4];
#pragma unroll
    for (int i = 0; i < 4; i++) {
        aS[i] = make_float4(0.f, 0.f, 0.f, 0.f);
        aD[i] = make_float4(0.f, 0.f, 0.f, 0.f);
        aH[i] = make_float4(0.f, 0.f, 0.f, 0.f);
    }

    // Head: W rows [0,128), src = A cols k, dst = A cols 128+k
    for (int kc = 0; kc < 128; kc += 16) {
        __syncthreads();
        for (int i = tid; i < 512; i += 256) {
            int rr = i >> 5, cc = (i & 31) * 4;
            *(float4*)&Wc[rr * 128 + cc] = ldg4(&W[(size_t)(kc + rr) * 128 + cc]);
        }
        __syncthreads();
#pragma unroll
        for (int kk = 0; kk < 16; kk++) {
            float4 w = *(float4*)&Wc[kk * 128 + c0];
#pragma unroll
            for (int i = 0; i < 4; i++) {
                float x = A[(r0 + i) * AS + kc + kk];
                float y = A[(r0 + i) * AS + 128 + kc + kk];
                aS[i].x += x * w.x; aS[i].y += x * w.y; aS[i].z += x * w.z; aS[i].w += x * w.w;
                aD[i].x += y * w.x; aD[i].y += y * w.y; aD[i].z += y * w.z; aD[i].w += y * w.w;
            }
        }
    }
    // Shared te: W rows [128,192), A cols [256,320)
    for (int kc = 0; kc < 64; kc += 16) {
        __syncthreads();
        for (int i = tid; i < 512; i += 256) {
            int rr = i >> 5, cc = (i & 31) * 4;
            *(float4*)&Wc[rr * 128 + cc] = ldg4(&W[(size_t)(128 + kc + rr) * 128 + cc]);
        }
        __syncthreads();
#pragma unroll
        for (int kk = 0; kk < 16; kk++) {
            float4 w = *(float4*)&Wc[kk * 128 + c0];
#pragma unroll
            for (int i = 0; i < 4; i++) {
                float x = A[(r0 + i) * AS + 256 + kc + kk];
                aH[i].x += x * w.x; aH[i].y += x * w.y; aH[i].z += x * w.z; aH[i].w += x * w.w;
            }
        }
    }

    float4 b4 = ldg4(&b[c0]);
#pragma unroll
    for (int i = 0; i < 4; i++) {
        int r = r0 + i;
        int e = e0 + r;
        if (e < E) {
            int s = __ldg(&src[e]), d = __ldg(&dst[e]);
            float4 ps = ldg4(&proj[(size_t)s * 128 + c0]);
            float4 pd = ldg4(&proj[(size_t)d * 128 + c0]);
            float4 os, od;
            os.x = fmaxf(aS[i].x + aH[i].x + b4.x + ps.x, 0.f);
            os.y = fmaxf(aS[i].y + aH[i].y + b4.y + ps.y, 0.f);
            os.z = fmaxf(aS[i].z + aH[i].z + b4.z + ps.z, 0.f);
            os.w = fmaxf(aS[i].w + aH[i].w + b4.w + ps.w, 0.f);
            od.x = fmaxf(aD[i].x + aH[i].x + b4.x + pd.x, 0.f);
            od.y = fmaxf(aD[i].y + aH[i].y + b4.y + pd.y, 0.f);
            od.z = fmaxf(aD[i].z + aH[i].z + b4.z + pd.z, 0.f);
            od.w = fmaxf(aD[i].w + aH[i].w + b4.w + pd.w, 0.f);
            *(float4*)&outS[(size_t)e * 128 + c0] = os;
            *(float4*)&outD[(size_t)e * 128 + c0] = od;
        }
    }
}

// ---------------------------------------------------------------------------
extern "C" void kernel_launch(void* const* d_in, const int* in_sizes, int n_in,
                              void* d_out, int out_size) {
    const float* nfeat = (const float*)d_in[0];
    const float* efeat = (const float*)d_in[1];
    const int*   src   = (const int*)d_in[2];
    const int*   dst   = (const int*)d_in[3];
    const float* ts    = (const float*)d_in[4];
    const float* Ws1 = (const float*)d_in[5];
    const float* bs1 = (const float*)d_in[6];
    const float* Wn1 = (const float*)d_in[7];
    const float* bn1 = (const float*)d_in[8];
    const float* om1 = (const float*)d_in[9];
    const float* ph1 = (const float*)d_in[10];
    const float* Ws2 = (const float*)d_in[11];
    const float* bs2 = (const float*)d_in[12];
    const float* Wn2 = (const float*)d_in[13];
    const float* bn2 = (const float*)d_in[14];
    const float* om2 = (const float*)d_in[15];
    const float* ph2 = (const float*)d_in[16];

    int Nn = in_sizes[0] / 64;
    int E  = in_sizes[2];

    float *cnt, *s1, *s2, *proj, *sf, *df;
    cudaGetSymbolAddress((void**)&cnt,  g_cnt);
    cudaGetSymbolAddress((void**)&s1,   g_sum1);
    cudaGetSymbolAddress((void**)&s2,   g_sum2);
    cudaGetSymbolAddress((void**)&proj, g_proj);
    cudaGetSymbolAddress((void**)&sf,   g_srcF);
    cudaGetSymbolAddress((void**)&df,   g_dstF);

    float* outv = (float*)d_out;
    int nTileBlocks = (Nn + 31) / 32;
    int eTileBlocks = (E + 31) / 32;

    k_zero<<<2048, 256>>>(cnt, s1, s2, Nn);
    k_agg1<<<2048, 256>>>(nfeat, efeat, src, dst, s1, cnt, E);
    k_proj<<<nTileBlocks, 256>>>(s1, cnt, Wn1, bn1, proj, Nn);
    k_layer1<<<eTileBlocks, 256>>>(nfeat, efeat, src, dst, ts, Ws1, bs1, om1, ph1,
                                   proj, sf, df, s2, E);
    k_proj<<<nTileBlocks, 256>>>(s2, cnt, Wn2, bn2, proj, Nn);
    k_layer2<<<eTileBlocks, 256>>>(sf, df, src, dst, ts, Ws2, bs2, om2, ph2,
                                   proj, outv, outv + (size_t)E * 128, E);
}

// round 6
// speedup vs baseline: 1.3943x; 1.3943x over previous
#include <cuda_runtime.h>
#include <math.h>
#include <stdint.h>

// Problem sizes (fixed by the dataset)
#define NN 100000
#define EE 500000

// Scratch (device globals; allocation-free per harness rules)
__device__ float g_cnt[NN];
__device__ float g_sum1[(size_t)NN * 128];
__device__ float g_sum2[(size_t)NN * 128];
__device__ float g_proj[(size_t)NN * 128];
__device__ float g_srcF[(size_t)EE * 128];
__device__ float g_dstF[(size_t)EE * 128];

__device__ __forceinline__ float4 ldg4(const float* p) {
    return __ldg((const float4*)p);
}

// Vectorized global reduction (no return)
__device__ __forceinline__ void red4(float* p, float4 v) {
    asm volatile("red.global.add.v4.f32 [%0], {%1,%2,%3,%4};"
                 :: "l"(p), "f"(v.x), "f"(v.y), "f"(v.z), "f"(v.w) : "memory");
}

// acc += a.{x,y,z,w} * w{0,1,2,3}  (16 FFMA) — function, not macro (hygiene)
__device__ __forceinline__ void fma4(float4& acc, float4 a,
                                     float4 w0, float4 w1, float4 w2, float4 w3) {
    acc.x = fmaf(a.x, w0.x, acc.x); acc.y = fmaf(a.x, w0.y, acc.y);
    acc.z = fmaf(a.x, w0.z, acc.z); acc.w = fmaf(a.x, w0.w, acc.w);
    acc.x = fmaf(a.y, w1.x, acc.x); acc.y = fmaf(a.y, w1.y, acc.y);
    acc.z = fmaf(a.y, w1.z, acc.z); acc.w = fmaf(a.y, w1.w, acc.w);
    acc.x = fmaf(a.z, w2.x, acc.x); acc.y = fmaf(a.z, w2.y, acc.y);
    acc.z = fmaf(a.z, w2.z, acc.z); acc.w = fmaf(a.z, w2.w, acc.w);
    acc.x = fmaf(a.w, w3.x, acc.x); acc.y = fmaf(a.w, w3.y, acc.y);
    acc.z = fmaf(a.w, w3.z, acc.z); acc.w = fmaf(a.w, w3.w, acc.w);
}

// ---------------------------------------------------------------------------
// Zero cnt + sum1 + sum2
// ---------------------------------------------------------------------------
__global__ void k_zero(float* cnt, float* s1, float* s2, int n) {
    int i = blockIdx.x * blockDim.x + threadIdx.x;
    int stride = gridDim.x * blockDim.x;
    int t4 = n * 32;
    float4 z = make_float4(0.f, 0.f, 0.f, 0.f);
    for (int j = i; j < t4; j += stride) {
        ((float4*)s1)[j] = z;
        ((float4*)s2)[j] = z;
    }
    for (int j = i; j < n; j += stride) cnt[j] = 0.f;
}

// ---------------------------------------------------------------------------
// Layer-1 aggregation: sum1[src] += [nfeat[dst], efeat]; sum1[dst] += [nfeat[src], efeat]
// ---------------------------------------------------------------------------
__global__ void k_agg1(const float* __restrict__ nfeat, const float* __restrict__ efeat,
                       const int* __restrict__ src, const int* __restrict__ dst,
                       float* sum1, float* cnt, int E) {
    int warp = (blockIdx.x * blockDim.x + threadIdx.x) >> 5;
    int lane = threadIdx.x & 31;
    int nw = (gridDim.x * blockDim.x) >> 5;
    for (int e = warp; e < E; e += nw) {
        int s = __ldg(&src[e]);
        int d = __ldg(&dst[e]);
        float4 vs, vd;
        int off;
        if (lane < 16) {
            off = lane * 4;
            vs = ldg4(&nfeat[(size_t)d * 64 + off]);
            vd = ldg4(&nfeat[(size_t)s * 64 + off]);
        } else {
            int q = (lane - 16) * 4;
            off = 64 + q;
            float4 ef = ldg4(&efeat[(size_t)e * 64 + q]);
            vs = ef; vd = ef;
        }
        red4(&sum1[(size_t)s * 128 + off], vs);
        red4(&sum1[(size_t)d * 128 + off], vd);
        if (lane == 0) {
            atomicAdd(&cnt[s], 1.f);
            atomicAdd(&cnt[d], 1.f);
        }
    }
}

// ---------------------------------------------------------------------------
// Node projection: proj[n] = (sum[n]/max(cnt,1)) @ W[128,128] + b
// ---------------------------------------------------------------------------
__global__ __launch_bounds__(256, 2) void k_proj(
    const float* __restrict__ sum, const float* __restrict__ cnt,
    const float* __restrict__ W, const float* __restrict__ b,
    float* __restrict__ proj, int Nn) {
    __shared__ float A[32 * 128];
    __shared__ float Wc[16 * 128];
    __shared__ float invS[32];
    int tid = threadIdx.x;
    int n0 = blockIdx.x * 32;

    if (tid < 32) {
        int n = n0 + tid;
        float c = 1.f;
        if (n < Nn) c = fmaxf(__ldg(&cnt[n]), 1.f);
        invS[tid] = 1.f / c;
    }
    __syncthreads();
    for (int i = tid; i < 32 * 32; i += 256) {
        int r = i >> 5, q = (i & 31) * 4;
        int n = n0 + r;
        float4 v = make_float4(0.f, 0.f, 0.f, 0.f);
        if (n < Nn) {
            v = ldg4(&sum[(size_t)n * 128 + q]);
            float s = invS[r];
            v.x *= s; v.y *= s; v.z *= s; v.w *= s;
        }
        *(float4*)&A[r * 128 + q] = v;
    }

    int r0 = (tid >> 5) * 4, c0 = (tid & 31) * 4;
    float4 acc[4];
#pragma unroll
    for (int i = 0; i < 4; i++) acc[i] = make_float4(0.f, 0.f, 0.f, 0.f);

    for (int kc = 0; kc < 128; kc += 16) {
        __syncthreads();
        for (int i = tid; i < 512; i += 256) {
            int rr = i >> 5, cc = (i & 31) * 4;
            *(float4*)&Wc[rr * 128 + cc] = ldg4(&W[(size_t)(kc + rr) * 128 + cc]);
        }
        __syncthreads();
#pragma unroll
        for (int kk = 0; kk < 16; kk += 4) {
            float4 w0 = *(float4*)&Wc[(kk + 0) * 128 + c0];
            float4 w1 = *(float4*)&Wc[(kk + 1) * 128 + c0];
            float4 w2 = *(float4*)&Wc[(kk + 2) * 128 + c0];
            float4 w3 = *(float4*)&Wc[(kk + 3) * 128 + c0];
#pragma unroll
            for (int i = 0; i < 4; i++) {
                float4 a = *(float4*)&A[(r0 + i) * 128 + kc + kk];
                fma4(acc[i], a, w0, w1, w2, w3);
            }
        }
    }

    float4 b4 = ldg4(&b[c0]);
#pragma unroll
    for (int i = 0; i < 4; i++) {
        int n = n0 + r0 + i;
        if (n < Nn) {
            float4 o;
            o.x = acc[i].x + b4.x; o.y = acc[i].y + b4.y;
            o.z = acc[i].z + b4.z; o.w = acc[i].w + b4.w;
            *(float4*)&proj[(size_t)n * 128 + c0] = o;
        }
    }
}

// ---------------------------------------------------------------------------
// Layer-1 edge kernel. 128 threads, 32 edges/block, thread tile 8 rows x 4 cols.
// A layout per edge (AS=256): [0,64)=nfeat[src], [64,128)=nfeat[dst],
//                             [128,192)=efeat, [192,256)=te
// W rows: [0,64) head, [64,192) shared (efeat,te).
// ---------------------------------------------------------------------------
__global__ __launch_bounds__(128, 3) void k_layer1(
    const float* __restrict__ nfeat, const float* __restrict__ efeat,
    const int* __restrict__ src, const int* __restrict__ dst, const float* __restrict__ ts,
    const float* __restrict__ W, const float* __restrict__ b,
    const float* __restrict__ omega, const float* __restrict__ phase,
    const float* __restrict__ proj, float* __restrict__ outS, float* __restrict__ outD,
    float* __restrict__ sum2, int E) {
    const int AS = 256;
    __shared__ float A[32 * 256];   // 32KB
    __shared__ float Wc[16 * 128];  // 8KB
    __shared__ int sI[32], dI[32];
    __shared__ float tsS[32];
    int tid = threadIdx.x;
    int lane = tid & 31;
    int e0 = blockIdx.x * 32;

    if (tid < 32) {
        int e = e0 + tid;
        bool ok = e < E;
        sI[tid] = ok ? __ldg(&src[e]) : 0;
        dI[tid] = ok ? __ldg(&dst[e]) : 0;
        tsS[tid] = ok ? __ldg(&ts[e]) : 0.f;
    }
    __syncthreads();

    // Fill A: 48 float4 per edge
    for (int i = tid; i < 32 * 48; i += 128) {
        int r = i / 48, p = i % 48;
        int e = e0 + r;
        bool ok = e < E;
        float4 v = make_float4(0.f, 0.f, 0.f, 0.f);
        int col;
        if (p < 16) {
            col = p * 4;
            if (ok) v = ldg4(&nfeat[(size_t)sI[r] * 64 + p * 4]);
        } else if (p < 32) {
            col = 64 + (p - 16) * 4;
            if (ok) v = ldg4(&nfeat[(size_t)dI[r] * 64 + (p - 16) * 4]);
        } else {
            col = 128 + (p - 32) * 4;
            if (ok) v = ldg4(&efeat[(size_t)e * 64 + (p - 32) * 4]);
        }
        *(float4*)&A[r * AS + col] = v;
    }
    // te = cos(ts*omega + phase), cols [192,256)
    for (int i = tid; i < 32 * 16; i += 128) {
        int r = i >> 4, q = (i & 15) * 4;
        float t = tsS[r];
        float4 v;
        v.x = cosf(t * __ldg(&omega[q + 0]) + __ldg(&phase[q + 0]));
        v.y = cosf(t * __ldg(&omega[q + 1]) + __ldg(&phase[q + 1]));
        v.z = cosf(t * __ldg(&omega[q + 2]) + __ldg(&phase[q + 2]));
        v.w = cosf(t * __ldg(&omega[q + 3]) + __ldg(&phase[q + 3]));
        *(float4*)&A[r * AS + 192 + q] = v;
    }

    int r0 = (tid >> 5) * 8;   // warp -> 8 rows
    int c0 = lane * 4;         // lane -> 4 cols
    float4 aS[8], aD[8], aH[8];
#pragma unroll
    for (int i = 0; i < 8; i++) {
        aS[i] = make_float4(0.f, 0.f, 0.f, 0.f);
        aD[i] = make_float4(0.f, 0.f, 0.f, 0.f);
        aH[i] = make_float4(0.f, 0.f, 0.f, 0.f);
    }

    // Head: W rows [0,64); src = A cols k, dst = A cols 64+k
    for (int kc = 0; kc < 64; kc += 16) {
        __syncthreads();
        for (int i = tid; i < 512; i += 128) {
            int rr = i >> 5, cc = (i & 31) * 4;
            *(float4*)&Wc[rr * 128 + cc] = ldg4(&W[(size_t)(kc + rr) * 128 + cc]);
        }
        __syncthreads();
#pragma unroll
        for (int kk = 0; kk < 16; kk += 4) {
            float4 w0 = *(float4*)&Wc[(kk + 0) * 128 + c0];
            float4 w1 = *(float4*)&Wc[(kk + 1) * 128 + c0];
            float4 w2 = *(float4*)&Wc[(kk + 2) * 128 + c0];
            float4 w3 = *(float4*)&Wc[(kk + 3) * 128 + c0];
#pragma unroll
            for (int r = 0; r < 8; r++) {
                const float* Ar = &A[(r0 + r) * AS];
                float4 xs = *(float4*)&Ar[kc + kk];
                float4 xd = *(float4*)&Ar[64 + kc + kk];
                fma4(aS[r], xs, w0, w1, w2, w3);
                fma4(aD[r], xd, w0, w1, w2, w3);
            }
        }
    }
    // Shared: W rows [64,192); A cols [128,256)
    for (int kc = 0; kc < 128; kc += 16) {
        __syncthreads();
        for (int i = tid; i < 512; i += 128) {
            int rr = i >> 5, cc = (i & 31) * 4;
            *(float4*)&Wc[rr * 128 + cc] = ldg4(&W[(size_t)(64 + kc + rr) * 128 + cc]);
        }
        __syncthreads();
#pragma unroll
        for (int kk = 0; kk < 16; kk += 4) {
            float4 w0 = *(float4*)&Wc[(kk + 0) * 128 + c0];
            float4 w1 = *(float4*)&Wc[(kk + 1) * 128 + c0];
            float4 w2 = *(float4*)&Wc[(kk + 2) * 128 + c0];
            float4 w3 = *(float4*)&Wc[(kk + 3) * 128 + c0];
#pragma unroll
            for (int r = 0; r < 8; r++) {
                float4 xh = *(float4*)&A[(r0 + r) * AS + 128 + kc + kk];
                fma4(aH[r], xh, w0, w1, w2, w3);
            }
        }
    }

    // Epilogue: bias + proj gather + relu; write scratch; fused layer-2 segment-sum
    float4 b4 = ldg4(&b[c0]);
#pragma unroll
    for (int i = 0; i < 8; i++) {
        int r = r0 + i;
        int e = e0 + r;
        if (e < E) {
            int s = sI[r], d = dI[r];
            float4 ps = ldg4(&proj[(size_t)s * 128 + c0]);
            float4 pd = ldg4(&proj[(size_t)d * 128 + c0]);
            float4 os, od;
            os.x = fmaxf(aS[i].x + aH[i].x + b4.x + ps.x, 0.f);
            os.y = fmaxf(aS[i].y + aH[i].y + b4.y + ps.y, 0.f);
            os.z = fmaxf(aS[i].z + aH[i].z + b4.z + ps.z, 0.f);
            os.w = fmaxf(aS[i].w + aH[i].w + b4.w + ps.w, 0.f);
            od.x = fmaxf(aD[i].x + aH[i].x + b4.x + pd.x, 0.f);
            od.y = fmaxf(aD[i].y + aH[i].y + b4.y + pd.y, 0.f);
            od.z = fmaxf(aD[i].z + aH[i].z + b4.z + pd.z, 0.f);
            od.w = fmaxf(aD[i].w + aH[i].w + b4.w + pd.w, 0.f);
            *(float4*)&outS[(size_t)e * 128 + c0] = os;
            *(float4*)&outD[(size_t)e * 128 + c0] = od;
            red4(&sum2[(size_t)s * 128 + c0], od);
            red4(&sum2[(size_t)d * 128 + c0], os);
        }
    }
}

// ---------------------------------------------------------------------------
// Layer-2 edge kernel. A layout per edge (AS=320):
//   [0,128)=srcF, [128,256)=dstF, [256,320)=te2
// W rows: [0,128) head, [128,192) te (shared). Writes final output.
// ---------------------------------------------------------------------------
__global__ __launch_bounds__(128, 3) void k_layer2(
    const float* __restrict__ fS, const float* __restrict__ fD,
    const int* __restrict__ src, const int* __restrict__ dst, const float* __restrict__ ts,
    const float* __restrict__ W, const float* __restrict__ b,
    const float* __restrict__ omega, const float* __restrict__ phase,
    const float* __restrict__ proj, float* __restrict__ outS, float* __restrict__ outD, int E) {
    const int AS = 320;
    __shared__ float A[32 * 320];   // 40KB
    __shared__ float Wc[16 * 128];  // 8KB  -> total 48KB static exactly
    int tid = threadIdx.x;
    int lane = tid & 31;
    int e0 = blockIdx.x * 32;

    // Fill A: 64 float4 per edge (srcF row + dstF row)
    for (int i = tid; i < 32 * 64; i += 128) {
        int r = i >> 6, p = i & 63;
        int e = e0 + r;
        bool ok = e < E;
        float4 v = make_float4(0.f, 0.f, 0.f, 0.f);
        int col;
        if (p < 32) {
            col = p * 4;
            if (ok) v = ldg4(&fS[(size_t)e * 128 + p * 4]);
        } else {
            col = 128 + (p - 32) * 4;
            if (ok) v = ldg4(&fD[(size_t)e * 128 + (p - 32) * 4]);
        }
        *(float4*)&A[r * AS + col] = v;
    }
    // te2, cols [256,320)
    for (int i = tid; i < 32 * 16; i += 128) {
        int r = i >> 4, q = (i & 15) * 4;
        int e = e0 + r;
        float t = (e < E) ? __ldg(&ts[e]) : 0.f;
        float4 v;
        v.x = cosf(t * __ldg(&omega[q + 0]) + __ldg(&phase[q + 0]));
        v.y = cosf(t * __ldg(&omega[q + 1]) + __ldg(&phase[q + 1]));
        v.z = cosf(t * __ldg(&omega[q + 2]) + __ldg(&phase[q + 2]));
        v.w = cosf(t * __ldg(&omega[q + 3]) + __ldg(&phase[q + 3]));
        *(float4*)&A[r * AS + 256 + q] = v;
    }

    int r0 = (tid >> 5) * 8;
    int c0 = lane * 4;
    float4 aS[8], aD[8], aH[8];
#pragma unroll
    for (int i = 0; i < 8; i++) {
        aS[i] = make_float4(0.f, 0.f, 0.f, 0.f);
        aD[i] = make_float4(0.f, 0.f, 0.f, 0.f);
        aH[i] = make_float4(0.f, 0.f, 0.f, 0.f);
    }

    // Head: W rows [0,128); src = A cols k, dst = A cols 128+k
    for (int kc = 0; kc < 128; kc += 16) {
        __syncthreads();
        for (int i = tid; i < 512; i += 128) {
            int rr = i >> 5, cc = (i & 31) * 4;
            *(float4*)&Wc[rr * 128 + cc] = ldg4(&W[(size_t)(kc + rr) * 128 + cc]);
        }
        __syncthreads();
#pragma unroll
        for (int kk = 0; kk < 16; kk += 4) {
            float4 w0 = *(float4*)&Wc[(kk + 0) * 128 + c0];
            float4 w1 = *(float4*)&Wc[(kk + 1) * 128 + c0];
            float4 w2 = *(float4*)&Wc[(kk + 2) * 128 + c0];
            float4 w3 = *(float4*)&Wc[(kk + 3) * 128 + c0];
#pragma unroll
            for (int r = 0; r < 8; r++) {
                const float* Ar = &A[(r0 + r) * AS];
                float4 xs = *(float4*)&Ar[kc + kk];
                float4 xd = *(float4*)&Ar[128 + kc + kk];
                fma4(aS[r], xs, w0, w1, w2, w3);
                fma4(aD[r], xd, w0, w1, w2, w3);
            }
        }
    }
    // Shared te: W rows [128,192); A cols [256,320)
    for (int kc = 0; kc < 64; kc += 16) {
        __syncthreads();
        for (int i = tid; i < 512; i += 128) {
            int rr = i >> 5, cc = (i & 31) * 4;
            *(float4*)&Wc[rr * 128 + cc] = ldg4(&W[(size_t)(128 + kc + rr) * 128 + cc]);
        }
        __syncthreads();
#pragma unroll
        for (int kk = 0; kk < 16; kk += 4) {
            float4 w0 = *(float4*)&Wc[(kk + 0) * 128 + c0];
            float4 w1 = *(float4*)&Wc[(kk + 1) * 128 + c0];
            float4 w2 = *(float4*)&Wc[(kk + 2) * 128 + c0];
            float4 w3 = *(float4*)&Wc[(kk + 3) * 128 + c0];
#pragma unroll
            for (int r = 0; r < 8; r++) {
                float4 xh = *(float4*)&A[(r0 + r) * AS + 256 + kc + kk];
                fma4(aH[r], xh, w0, w1, w2, w3);
            }
        }
    }

    float4 b4 = ldg4(&b[c0]);
#pragma unroll
    for (int i = 0; i < 8; i++) {
        int r = r0 + i;
        int e = e0 + r;
        if (e < E) {
            int s = __ldg(&src[e]), d = __ldg(&dst[e]);
            float4 ps = ldg4(&proj[(size_t)s * 128 + c0]);
            float4 pd = ldg4(&proj[(size_t)d * 128 + c0]);
            float4 os, od;
            os.x = fmaxf(aS[i].x + aH[i].x + b4.x + ps.x, 0.f);
            os.y = fmaxf(aS[i].y + aH[i].y + b4.y + ps.y, 0.f);
            os.z = fmaxf(aS[i].z + aH[i].z + b4.z + ps.z, 0.f);
            os.w = fmaxf(aS[i].w + aH[i].w + b4.w + ps.w, 0.f);
            od.x = fmaxf(aD[i].x + aH[i].x + b4.x + pd.x, 0.f);
            od.y = fmaxf(aD[i].y + aH[i].y + b4.y + pd.y, 0.f);
            od.z = fmaxf(aD[i].z + aH[i].z + b4.z + pd.z, 0.f);
            od.w = fmaxf(aD[i].w + aH[i].w + b4.w + pd.w, 0.f);
            *(float4*)&outS[(size_t)e * 128 + c0] = os;
            *(float4*)&outD[(size_t)e * 128 + c0] = od;
        }
    }
}

// ---------------------------------------------------------------------------
extern "C" void kernel_launch(void* const* d_in, const int* in_sizes, int n_in,
                              void* d_out, int out_size) {
    const float* nfeat = (const float*)d_in[0];
    const float* efeat = (const float*)d_in[1];
    const int*   src   = (const int*)d_in[2];
    const int*   dst   = (const int*)d_in[3];
    const float* ts    = (const float*)d_in[4];
    const float* Ws1 = (const float*)d_in[5];
    const float* bs1 = (const float*)d_in[6];
    const float* Wn1 = (const float*)d_in[7];
    const float* bn1 = (const float*)d_in[8];
    const float* om1 = (const float*)d_in[9];
    const float* ph1 = (const float*)d_in[10];
    const float* Ws2 = (const float*)d_in[11];
    const float* bs2 = (const float*)d_in[12];
    const float* Wn2 = (const float*)d_in[13];
    const float* bn2 = (const float*)d_in[14];
    const float* om2 = (const float*)d_in[15];
    const float* ph2 = (const float*)d_in[16];

    int Nn = in_sizes[0] / 64;
    int E  = in_sizes[2];

    float *cnt, *s1, *s2, *proj, *sf, *df;
    cudaGetSymbolAddress((void**)&cnt,  g_cnt);
    cudaGetSymbolAddress((void**)&s1,   g_sum1);
    cudaGetSymbolAddress((void**)&s2,   g_sum2);
    cudaGetSymbolAddress((void**)&proj, g_proj);
    cudaGetSymbolAddress((void**)&sf,   g_srcF);
    cudaGetSymbolAddress((void**)&df,   g_dstF);

    float* outv = (float*)d_out;
    int nTileBlocks = (Nn + 31) / 32;
    int eTileBlocks = (E + 31) / 32;

    k_zero<<<2048, 256>>>(cnt, s1, s2, Nn);
    k_agg1<<<2048, 256>>>(nfeat, efeat, src, dst, s1, cnt, E);
    k_proj<<<nTileBlocks, 256>>>(s1, cnt, Wn1, bn1, proj, Nn);
    k_layer1<<<eTileBlocks, 128>>>(nfeat, efeat, src, dst, ts, Ws1, bs1, om1, ph1,
                                   proj, sf, df, s2, E);
    k_proj<<<nTileBlocks, 256>>>(s2, cnt, Wn2, bn2, proj, Nn);
    k_layer2<<<eTileBlocks, 128>>>(sf, df, src, dst, ts, Ws2, bs2, om2, ph2,
                                   proj, outv, outv + (size_t)E * 128, E);
}